// round 15
// baseline (speedup 1.0000x reference)
#include <cuda_runtime.h>

// LossFunction: fused IoU + smooth-L1 multi-loss over (B=256, N=8192, F=13).
//
// R15 = R13 (coalesced float4, loop-invariant %13 indexing via THREADS=416)
// + EXPLICIT LOAD BATCHING: 8 LDG.128s issued back-to-back per batch before
// any compute, so ptxas cannot serialize them (R3-vs-R13 evidence: achieved
// BW tracks batched loads/thread, not issue%). K_ITERS=16, ROWS_TILE=2048,
// launch_bounds(416,2) -> reg ceiling ~78 keeps the batch live.

#define F 13
#define THREADS 416            // 13 * 32
#define K_ITERS 16
#define KB 4                   // k-iterations per load batch
#define ROWS_TILE 2048         // 4*416*16/13
#define NWARPS (THREADS / 32)  // 13
#define MAX_BLOCKS 4096

__device__ float        g_partials[MAX_BLOCKS];
__device__ unsigned int g_ticket = 0;

__device__ __forceinline__ float huber(float a, float b) {
    float d = fabsf(a - b);
    return d < 1.0f ? 0.5f * d * d : d - 0.5f;
}

__global__ __launch_bounds__(THREADS, 2)
void loss_kernel(const float* __restrict__ tg,
                 const float* __restrict__ pr,
                 float* __restrict__ out,
                 long long rows,
                 float c1, float w2, float w4, float w3) {
    // Box staging: sbox[row][0..3]=target box, [4..7]=pred box. 64KB.
    __shared__ __align__(16) float sbox[ROWS_TILE * 8];
    __shared__ float warp_part[NWARPS];
    __shared__ bool  is_last;

    long long tile_row0 = (long long)blockIdx.x * ROWS_TILE;
    long long rem       = rows - tile_row0;
    int nrows = rem < ROWS_TILE ? (int)rem : ROWS_TILE;

    int t = threadIdx.x;
    float acc = 0.0f;

    if (nrows == ROWS_TILE) {
        const float4* t4 = (const float4*)(tg + tile_row0 * F);
        const float4* p4 = (const float4*)(pr + tile_row0 * F);

        // ---- Loop-invariant per-thread constants (THREADS % 13 == 0) ----
        int e0 = 4 * t;
        int f_[4], rb_[4];
        float w_[4];
        bool b_[4];
        #pragma unroll
        for (int j = 0; j < 4; j++) {
            int e = e0 + j;
            rb_[j] = e / 13;              // row base within tile
            f_[j]  = e - 13 * rb_[j];     // feature index (invariant over k)
            w_[j]  = (f_[j] < 4) ? w2 : ((f_[j] < 12) ? w4 : w3);
            b_[j]  = (f_[j] < 4);
        }

        float a0 = 0.0f, a1 = 0.0f;
        #pragma unroll
        for (int kb = 0; kb < K_ITERS; kb += KB) {
            // -- batch: 8 independent LDG.128s, no compute in between --
            float4 tv[KB], pv[KB];
            #pragma unroll
            for (int u = 0; u < KB; u++) {
                tv[u] = __ldg(t4 + t + (kb + u) * THREADS);
                pv[u] = __ldg(p4 + t + (kb + u) * THREADS);
            }
            // -- consume batch --
            #pragma unroll
            for (int u = 0; u < KB; u++) {
                float ta[4] = {tv[u].x, tv[u].y, tv[u].z, tv[u].w};
                float pa[4] = {pv[u].x, pv[u].y, pv[u].z, pv[u].w};
                int rowk = 128 * (kb + u);   // rows advance 128 per k-iter
                #pragma unroll
                for (int j = 0; j < 4; j++) {
                    if (j & 1) a1 += w_[j] * huber(ta[j], pa[j]);
                    else       a0 += w_[j] * huber(ta[j], pa[j]);
                    if (b_[j]) {             // invariant predicate
                        int base = (rb_[j] + rowk) * 8 + f_[j];
                        sbox[base]     = ta[j];
                        sbox[base + 4] = pa[j];
                    }
                }
            }
        }
        acc = a0 + a1;
    } else {
        // Generic tail tile (not hit for the benchmark shape).
        for (int r = t; r < nrows; r += THREADS) {
            const float* tr = tg + (tile_row0 + r) * F;
            const float* pq = pr + (tile_row0 + r) * F;
            #pragma unroll
            for (int f = 0; f < F; f++) {
                float wgt = (f < 4) ? w2 : ((f < 12) ? w4 : w3);
                float tv = __ldg(tr + f), pv = __ldg(pq + f);
                acc += wgt * huber(tv, pv);
                if (f < 4) {
                    sbox[r * 8 + f]     = tv;
                    sbox[r * 8 + 4 + f] = pv;
                }
            }
        }
    }
    __syncthreads();

    // ---- IoU pass from smem (conflict-free float4 LDS) ----
    for (int r = t; r < nrows; r += THREADS) {
        float4 tb = *(const float4*)&sbox[r * 8];
        float4 pb = *(const float4*)&sbox[r * 8 + 4];
        float xx1 = fmaxf(tb.x, pb.x);
        float yy1 = fmaxf(tb.y, pb.y);
        float xx2 = fminf(tb.z, pb.z);
        float yy2 = fminf(tb.w, pb.w);
        float w = fmaxf(xx2 - xx1, 0.0f);
        float h = fmaxf(yy2 - yy1, 0.0f);
        float inter = w * h;
        float area1 = (tb.z - tb.x) * (tb.w - tb.y);
        float area2 = (pb.z - pb.x) * (pb.w - pb.y);
        float iou = inter / (area1 + area2 - inter + 1e-7f);
        acc += c1 * huber(1.0f, iou);
    }

    // ---- Block reduction ----
    #pragma unroll
    for (int off = 16; off > 0; off >>= 1)
        acc += __shfl_xor_sync(0xFFFFFFFFu, acc, off);

    int lane = t & 31;
    int wid  = t >> 5;
    if (lane == 0) warp_part[wid] = acc;
    __syncthreads();

    if (wid == 0) {
        float v = lane < NWARPS ? warp_part[lane] : 0.0f;
        #pragma unroll
        for (int off = 8; off > 0; off >>= 1)
            v += __shfl_xor_sync(0xFFFFFFFFu, v, off);
        if (lane == 0) {
            g_partials[blockIdx.x] = v;
            __threadfence();
            unsigned tk = atomicAdd(&g_ticket, 1u);
            is_last = (tk == gridDim.x - 1);
        }
    }
    __syncthreads();

    // Last block reduces all partials (deterministic order) and writes out.
    if (is_last) {
        __threadfence();
        float v = 0.0f;
        for (int i = t; i < (int)gridDim.x; i += THREADS)
            v += g_partials[i];
        #pragma unroll
        for (int off = 16; off > 0; off >>= 1)
            v += __shfl_xor_sync(0xFFFFFFFFu, v, off);
        if (lane == 0) warp_part[wid] = v;
        __syncthreads();
        if (wid == 0) {
            float s = lane < NWARPS ? warp_part[lane] : 0.0f;
            #pragma unroll
            for (int off = 8; off > 0; off >>= 1)
                s += __shfl_xor_sync(0xFFFFFFFFu, s, off);
            if (lane == 0) {
                out[0] = s;
                g_ticket = 0;   // reset for next graph replay
            }
        }
    }
}

extern "C" void kernel_launch(void* const* d_in, const int* in_sizes, int n_in,
                              void* d_out, int out_size) {
    const float* targets = (const float*)d_in[0];
    const float* preds   = (const float*)d_in[1];
    float* out = (float*)d_out;

    long long total = (long long)in_sizes[0];
    long long rows  = total / F;  // B*N = 2,097,152

    float inv = 1.0f / (float)rows;
    // Exact per-feature weights:
    float w2 = inv * 0.25f;    // f in [0,4)  : loss2 mean over rows*4
    float w4 = inv * 0.0625f;  // f in [4,12) : 0.5 * mean over rows*8
    float w3 = inv;            // f == 12     : loss3 mean over rows
    float c1 = inv;            // loss1 mean

    int grid = (int)((rows + ROWS_TILE - 1) / ROWS_TILE);  // 1024 exact
    if (grid > MAX_BLOCKS) grid = MAX_BLOCKS;  // safety (not hit for bench shape)

    loss_kernel<<<grid, THREADS>>>(targets, preds, out, rows, c1, w2, w4, w3);
}

// round 16
// speedup vs baseline: 1.0487x; 1.0487x over previous
#include <cuda_runtime.h>

// LossFunction: fused IoU + smooth-L1 multi-loss over (B=256, N=8192, F=13).
//
// R16: chunk-class compaction.
//  - Stream: coalesced float4, uniform base weight w4 (R4 algebra), so the
//    per-element loop is just 4 hubers. A chunk's relevance to IoU/corrections
//    depends only on cm = chunk%13: chunks cm in {0,3,4,6,7,9,10,12} contain
//    ALL box + f12 floats of their 4-row group at static positions. Those 8
//    chunks/group are STS.128'd whole into compacted smem (swizzled by group
//    for conflict-free access). cm and group are maintained incrementally.
//  - Extract: thread g reads its group's 8 chunks (static offsets), computes
//    4x IoU + (w2-w4)*box hubers + (w3-w4)*f12 huber.
//  - 128 thr, 512-row tile (1664 = 13*128 chunks exact), 32KB smem ->
//    7 blocks/SM = 28 warps. Single kernel, ticket last-block reduction.

#define F 13
#define THREADS 128
#define ROWS_TILE 512
#define GROUPS (ROWS_TILE / 4)        // 128 groups of 4 rows
#define CHUNKS (ROWS_TILE * F / 4)    // 1664 = 13 * 128
#define MAX_BLOCKS 4096
#define CHUNKMASK 0x16D9u             // bits {0,3,4,6,7,9,10,12}

__device__ float        g_partials[MAX_BLOCKS];
__device__ unsigned int g_ticket = 0;

__device__ __forceinline__ float huber(float a, float b) {
    float d = fabsf(a - b);
    return d < 1.0f ? 0.5f * d * d : d - 0.5f;
}

__device__ __forceinline__ float row_loss(
    float t0, float t1, float t2, float t3, float t12,
    float p0, float p1, float p2, float p3, float p12,
    float c1, float corr2, float corr3) {
    float s = corr2 * (huber(t0, p0) + huber(t1, p1) +
                       huber(t2, p2) + huber(t3, p3));
    s += corr3 * huber(t12, p12);
    float xx1 = fmaxf(t0, p0);
    float yy1 = fmaxf(t1, p1);
    float xx2 = fminf(t2, p2);
    float yy2 = fminf(t3, p3);
    float w = fmaxf(xx2 - xx1, 0.0f);
    float h = fmaxf(yy2 - yy1, 0.0f);
    float inter = w * h;
    float a1 = (t2 - t0) * (t3 - t1);
    float a2 = (p2 - p0) * (p3 - p1);
    float iou = inter / (a1 + a2 - inter + 1e-7f);
    return s + c1 * huber(1.0f, iou);
}

__global__ __launch_bounds__(THREADS, 7)
void loss_kernel(const float* __restrict__ tg,
                 const float* __restrict__ pr,
                 float* __restrict__ out,
                 long long rows,
                 float c1, float wbase, float corr2, float corr3) {
    // Compacted chunk store: 8 chunks (float4) per group, swizzled by group.
    __shared__ __align__(16) float st_c[GROUPS * 32];   // 16KB
    __shared__ __align__(16) float sp_c[GROUPS * 32];   // 16KB
    __shared__ float warp_part[THREADS / 32];
    __shared__ bool  is_last;

    long long tile_row0 = (long long)blockIdx.x * ROWS_TILE;
    long long rem       = rows - tile_row0;
    int nrows = rem < ROWS_TILE ? (int)rem : ROWS_TILE;

    int t = threadIdx.x;
    float acc = 0.0f;

    if (nrows == ROWS_TILE) {
        const float4* t4 = (const float4*)(tg + tile_row0 * F);
        const float4* p4 = (const float4*)(pr + tile_row0 * F);

        int cm = t % 13;     // chunk index mod 13  (incrementally maintained)
        int cd = t / 13;     // group index         (incrementally maintained)

        float a0 = 0.0f, a1 = 0.0f;
        #pragma unroll
        for (int k = 0; k < 13; k++) {
            int c = t + k * THREADS;
            float4 tv = __ldg(t4 + c);
            float4 pv = __ldg(p4 + c);
            a0 += huber(tv.x, pv.x) + huber(tv.z, pv.z);
            a1 += huber(tv.y, pv.y) + huber(tv.w, pv.w);

            if ((CHUNKMASK >> cm) & 1u) {
                int m   = __popc(CHUNKMASK & ((1u << cm) - 1u));  // rank 0..7
                int off = cd * 32 + (((m + cd) & 7) << 2);        // swizzled
                *(float4*)(st_c + off) = tv;
                *(float4*)(sp_c + off) = pv;
            }
            // advance by 128 chunks: 128 = 13*9 + 11
            bool wrap = (cm >= 2);
            cm += wrap ? -2 : 11;
            cd += wrap ? 10 : 9;
        }
        acc = (a0 + a1) * wbase;
    } else {
        // Generic tail tile (not hit for the benchmark shape).
        for (int r = t; r < nrows; r += THREADS) {
            const float* tr = tg + (tile_row0 + r) * F;
            const float* pq = pr + (tile_row0 + r) * F;
            float tv[F], pv[F];
            #pragma unroll
            for (int f = 0; f < F; f++) { tv[f] = __ldg(tr + f); pv[f] = __ldg(pq + f); }
            float s = 0.0f;
            #pragma unroll
            for (int f = 0; f < F; f++) s += wbase * huber(tv[f], pv[f]);
            acc += s + row_loss(tv[0], tv[1], tv[2], tv[3], tv[12],
                                pv[0], pv[1], pv[2], pv[3], pv[12],
                                c1, corr2, corr3);
        }
    }
    __syncthreads();

    // ---- Extraction: thread g owns group g (4 rows). All offsets static. ----
    if (nrows == ROWS_TILE) {
        int g = t;
        #define LDC(arr, m) (*(const float4*)((arr) + g * 32 + ((((m) + g) & 7) << 2)))
        float4 T0 = LDC(st_c, 0), T1 = LDC(st_c, 1);
        float4 P0 = LDC(sp_c, 0), P1 = LDC(sp_c, 1);
        // row 0: box = floats 0..3 (m0), f12 = float 12 (m1.x)
        acc += row_loss(T0.x, T0.y, T0.z, T0.w, T1.x,
                        P0.x, P0.y, P0.z, P0.w, P1.x, c1, corr2, corr3);

        float4 T2 = LDC(st_c, 2), T3 = LDC(st_c, 3);
        float4 P2 = LDC(sp_c, 2), P3 = LDC(sp_c, 3);
        // row 1: box = floats 13..16 (m1.y,m1.z,m1.w,m2.x), f12 = float 25 (m3.y)
        acc += row_loss(T1.y, T1.z, T1.w, T2.x, T3.y,
                        P1.y, P1.z, P1.w, P2.x, P3.y, c1, corr2, corr3);

        float4 T4 = LDC(st_c, 4), T5 = LDC(st_c, 5);
        float4 P4 = LDC(sp_c, 4), P5 = LDC(sp_c, 5);
        // row 2: box = floats 26..29 (m3.z,m3.w,m4.x,m4.y), f12 = float 38 (m5.z)
        acc += row_loss(T3.z, T3.w, T4.x, T4.y, T5.z,
                        P3.z, P3.w, P4.x, P4.y, P5.z, c1, corr2, corr3);

        float4 T6 = LDC(st_c, 6), T7 = LDC(st_c, 7);
        float4 P6 = LDC(sp_c, 6), P7 = LDC(sp_c, 7);
        // row 3: box = floats 39..42 (m5.w,m6.x,m6.y,m6.z), f12 = float 51 (m7.w)
        acc += row_loss(T5.w, T6.x, T6.y, T6.z, T7.w,
                        P5.w, P6.x, P6.y, P6.z, P7.w, c1, corr2, corr3);
        #undef LDC
    }

    // ---- Block reduction ----
    #pragma unroll
    for (int off = 16; off > 0; off >>= 1)
        acc += __shfl_xor_sync(0xFFFFFFFFu, acc, off);

    int lane = t & 31;
    int wid  = t >> 5;
    if (lane == 0) warp_part[wid] = acc;
    __syncthreads();

    if (wid == 0) {
        float v = lane < (THREADS / 32) ? warp_part[lane] : 0.0f;
        #pragma unroll
        for (int off = 2; off > 0; off >>= 1)
            v += __shfl_xor_sync(0xFFFFFFFFu, v, off);
        if (lane == 0) {
            g_partials[blockIdx.x] = v;
            __threadfence();
            unsigned tk = atomicAdd(&g_ticket, 1u);
            is_last = (tk == gridDim.x - 1);
        }
    }
    __syncthreads();

    // Last block reduces all partials (deterministic order) and writes out.
    if (is_last) {
        __threadfence();
        float v = 0.0f;
        for (int i = t; i < (int)gridDim.x; i += THREADS)
            v += g_partials[i];
        #pragma unroll
        for (int off = 16; off > 0; off >>= 1)
            v += __shfl_xor_sync(0xFFFFFFFFu, v, off);
        if (lane == 0) warp_part[wid] = v;
        __syncthreads();
        if (wid == 0) {
            float s = lane < (THREADS / 32) ? warp_part[lane] : 0.0f;
            #pragma unroll
            for (int off = 2; off > 0; off >>= 1)
                s += __shfl_xor_sync(0xFFFFFFFFu, s, off);
            if (lane == 0) {
                out[0] = s;
                g_ticket = 0;   // reset for next graph replay
            }
        }
    }
}

extern "C" void kernel_launch(void* const* d_in, const int* in_sizes, int n_in,
                              void* d_out, int out_size) {
    const float* targets = (const float*)d_in[0];
    const float* preds   = (const float*)d_in[1];
    float* out = (float*)d_out;

    long long total = (long long)in_sizes[0];
    long long rows  = total / F;  // B*N = 2,097,152

    float inv = 1.0f / (float)rows;
    // Per-element weights: f<4: inv/4; 4<=f<12: inv/16; f==12: inv.
    float wbase = inv * 0.0625f;          // uniform base (w4)
    float corr2 = inv * 0.25f - wbase;    // extra for f<4
    float corr3 = inv - wbase;            // extra for f==12
    float c1    = inv;                    // loss1 mean

    int grid = (int)((rows + ROWS_TILE - 1) / ROWS_TILE);  // 4096 exact
    if (grid > MAX_BLOCKS) grid = MAX_BLOCKS;  // safety (not hit for bench shape)

    loss_kernel<<<grid, THREADS>>>(targets, preds, out, rows,
                                   c1, wbase, corr2, corr3);
}